// round 14
// baseline (speedup 1.0000x reference)
#include <cuda_runtime.h>
#include <cuda_fp16.h>
#include <math.h>
#include <stdint.h>

#define NN 30000
#define EE 480000
#define EPLUS (EE + NN)
#define NEG 0.2f

// ---------------- scratch (static device globals; no allocation) ----------------
__device__ float  g_hn[(size_t)NN * 512];   // final-layer f32 (heads input)
__device__ float  g_hp[(size_t)NN * 512];   // per-layer GEMM output (f32)
__device__ __half g_hph[(size_t)NN * 512];  // fp16 copy of hp (agg gather path)
__device__ __half g_Ah[(size_t)NN * 512];   // activations fp16 hi
__device__ __half g_Al[(size_t)NN * 512];   // activations fp16 lo
__device__ __half g_Bh[3 * 512 * 512];      // weights fp16 hi, per-layer, [N][K]
__device__ __half g_Bl[3 * 512 * 512];      // weights fp16 lo, per-layer
__device__ float  g_s [NN * 8];
__device__ float  g_d [NN * 8];
__device__ float  g_w [(size_t)EPLUS * 8];  // per-(edge,head) unnormalized weights
__device__ int    g_off[NN + 1];
__device__ int    g_cnt[NN];
__device__ int    g_cur[NN];
__device__ int    g_csr[EPLUS];
__device__ int    g_dstc[EPLUS];            // dst node of each CSR slot

// ---------------- helpers ----------------
__device__ __forceinline__ uint32_t smem_u32(const void* p) {
    return (uint32_t)__cvta_generic_to_shared(p);
}
__device__ __forceinline__ void cp_async16(uint32_t dst, const void* src, int src_bytes) {
    asm volatile("cp.async.cg.shared.global [%0], [%1], 16, %2;\n"
                 :: "r"(dst), "l"(src), "r"(src_bytes));
}
__device__ __forceinline__ void cp_commit() { asm volatile("cp.async.commit_group;\n"); }
template <int N>
__device__ __forceinline__ void cp_wait() { asm volatile("cp.async.wait_group %0;\n" :: "n"(N)); }

__device__ __forceinline__ void f16_split(float v, __half& hi, __half& lo) {
    hi = __float2half_rn(v);
    lo = __float2half_rn(v - __half2float(hi));
}

// fp16 mma m16n8k16, f32 accumulate
__device__ __forceinline__ void mma_f16(float* c, const uint32_t* a, const uint32_t* b) {
    asm volatile(
        "mma.sync.aligned.m16n8k16.row.col.f32.f16.f16.f32 "
        "{%0,%1,%2,%3}, {%4,%5,%6,%7}, {%8,%9}, {%0,%1,%2,%3};\n"
        : "+f"(c[0]), "+f"(c[1]), "+f"(c[2]), "+f"(c[3])
        : "r"(a[0]), "r"(a[1]), "r"(a[2]), "r"(a[3]), "r"(b[0]), "r"(b[1]));
}

// ---------------- CSR build ----------------
__global__ void k_init_counts() {
    int i = blockIdx.x * blockDim.x + threadIdx.x;
    if (i < NN) { g_cnt[i] = 1; g_cur[i] = 0; }
}

__global__ void k_count(const int* __restrict__ ei) {
    int i = blockIdx.x * blockDim.x + threadIdx.x;
    if (i < EE) atomicAdd(&g_cnt[ei[EE + i]], 1);
}

__global__ void k_scan() {
    __shared__ int sh[1024];
    __shared__ int carry;
    int tid = threadIdx.x;
    if (tid == 0) { carry = 0; g_off[0] = 0; }
    __syncthreads();
    for (int base = 0; base < NN; base += 1024) {
        int i = base + tid;
        int v = (i < NN) ? g_cnt[i] : 0;
        sh[tid] = v;
        __syncthreads();
        for (int o = 1; o < 1024; o <<= 1) {
            int t = (tid >= o) ? sh[tid - o] : 0;
            __syncthreads();
            sh[tid] += t;
            __syncthreads();
        }
        int inc = sh[tid] + carry;
        if (i < NN) g_off[i + 1] = inc;
        __syncthreads();
        if (tid == 1023) carry = inc;
        __syncthreads();
    }
}

__global__ void k_scatter(const int* __restrict__ ei) {
    int i = blockIdx.x * blockDim.x + threadIdx.x;
    if (i < EE) {
        int dst = ei[EE + i], src = ei[i];
        int p = atomicAdd(&g_cur[dst], 1);
        int slot = g_off[dst] + p;
        g_csr[slot]  = src;
        g_dstc[slot] = dst;
    } else if (i < EPLUS) {
        int n = i - EE;
        int p = atomicAdd(&g_cur[n], 1);
        int slot = g_off[n] + p;
        g_csr[slot]  = n;
        g_dstc[slot] = n;
    }
}

// ---------------- input projection: relu(x @ W_in + b) -> fp16 hi/lo ------------
__global__ void k_input_proj(const float* __restrict__ x, const float* __restrict__ W,
                             const float* __restrict__ b) {
    __shared__ float xs[8][32];
    int j  = threadIdx.x;
    int n0 = blockIdx.x * 8;
    if (j < 256) {
        int r = j >> 5, c = j & 31, n = n0 + r;
        xs[r][c] = (n < NN) ? x[n * 32 + c] : 0.f;
    }
    __syncthreads();
    float acc[8] = {0, 0, 0, 0, 0, 0, 0, 0};
#pragma unroll 8
    for (int k = 0; k < 32; k++) {
        float w = W[k * 512 + j];
#pragma unroll
        for (int r = 0; r < 8; r++) acc[r] += xs[r][k] * w;
    }
    float bb = b[j];
#pragma unroll
    for (int r = 0; r < 8; r++) {
        int n = n0 + r;
        if (n < NN) {
            float v = fmaxf(acc[r] + bb, 0.f);
            __half hi, lo;
            f16_split(v, hi, lo);
            g_Ah[(size_t)n * 512 + j] = hi;
            g_Al[(size_t)n * 512 + j] = lo;
        }
    }
}

// ---------------- weight conv: W[K][N] f32 -> transposed fp16 hi/lo [N][K] ------
__global__ void k_convB(const float* __restrict__ W, int layer) {
    int id = blockIdx.x * blockDim.x + threadIdx.x;  // 0..65535
    int n  = id >> 7;
    int k0 = (id & 127) * 4;
    size_t base = (size_t)layer * 512 * 512;
#pragma unroll
    for (int i = 0; i < 4; i++) {
        float v = __ldg(&W[(size_t)(k0 + i) * 512 + n]);
        __half hi, lo;
        f16_split(v, hi, lo);
        g_Bh[base + n * 512 + k0 + i] = hi;
        g_Bl[base + n * 512 + k0 + i] = lo;
    }
}

// ---------------- fp16-split tensor GEMM: g_hp = A[NN,512] @ B[512,512] ---------
// (R9 structure: CTA 128x128, 8 warps, k-tile 16, double-buffered cp.async)
// epilogue also writes fp16 copy g_hph for the aggregation gather.
#define GBUF 12288

__device__ __forceinline__ void stage16(__half* sm, int buf, int k0, int rowBase,
                                        int colBase, int r, int c, size_t bbase) {
    uint32_t base = buf * GBUF;
    uint32_t dA = smem_u32(&sm[base + r * 24 + c * 8]);
    int gr = rowBase + r;
    int sz = (gr < NN) ? 16 : 0;
    size_t aoff = (size_t)(gr < NN ? gr : NN - 1) * 512 + k0 + c * 8;
    cp_async16(dA, &g_Ah[aoff], sz);
    cp_async16(smem_u32(&sm[base + 3072 + r * 24 + c * 8]), &g_Al[aoff], sz);
    size_t boff = bbase + (size_t)(colBase + r) * 512 + k0 + c * 8;
    cp_async16(smem_u32(&sm[base + 6144 + r * 24 + c * 8]), &g_Bh[boff], 16);
    cp_async16(smem_u32(&sm[base + 9216 + r * 24 + c * 8]), &g_Bl[boff], 16);
}

__global__ __launch_bounds__(256, 2)
void k_gemm_f16(int layer) {
    extern __shared__ __half sm[];
    int tid  = threadIdx.x;
    int lane = tid & 31;
    int warp = tid >> 5;
    int warp_m = (warp & 1) * 64;
    int warp_n = (warp >> 1) * 32;
    int rowBase = blockIdx.y * 128;
    int colBase = blockIdx.x * 128;
    size_t bbase = (size_t)layer * 512 * 512;

    int ldr = tid >> 1, ldc = tid & 1;

    float acc[4][4][4];
#pragma unroll
    for (int i = 0; i < 4; i++)
#pragma unroll
        for (int j = 0; j < 4; j++)
#pragma unroll
            for (int k = 0; k < 4; k++) acc[i][j][k] = 0.f;

    stage16(sm, 0, 0, rowBase, colBase, ldr, ldc, bbase);
    cp_commit();

    for (int t = 0; t < 32; t++) {
        if (t < 31) {
            stage16(sm, (t + 1) & 1, (t + 1) * 16, rowBase, colBase, ldr, ldc, bbase);
            cp_commit();
            cp_wait<1>();
        } else {
            cp_wait<0>();
        }
        __syncthreads();

        const __half* A_hi = &sm[(t & 1) * GBUF];
        const __half* A_lo = A_hi + 3072;
        const __half* B_hi = A_hi + 6144;
        const __half* B_lo = A_hi + 9216;

        uint32_t bh[4][2], bl[4][2];
#pragma unroll
        for (int nt = 0; nt < 4; nt++) {
            int n0 = warp_n + nt * 8 + (lane >> 2);
            bh[nt][0] = *(const uint32_t*)&B_hi[n0 * 24 + (lane & 3) * 2];
            bh[nt][1] = *(const uint32_t*)&B_hi[n0 * 24 + 8 + (lane & 3) * 2];
            bl[nt][0] = *(const uint32_t*)&B_lo[n0 * 24 + (lane & 3) * 2];
            bl[nt][1] = *(const uint32_t*)&B_lo[n0 * 24 + 8 + (lane & 3) * 2];
        }
#pragma unroll
        for (int mt = 0; mt < 4; mt++) {
            int r0 = warp_m + mt * 16 + (lane >> 2);
            uint32_t ah[4], al[4];
            ah[0] = *(const uint32_t*)&A_hi[r0 * 24 + (lane & 3) * 2];
            ah[1] = *(const uint32_t*)&A_hi[(r0 + 8) * 24 + (lane & 3) * 2];
            ah[2] = *(const uint32_t*)&A_hi[r0 * 24 + 8 + (lane & 3) * 2];
            ah[3] = *(const uint32_t*)&A_hi[(r0 + 8) * 24 + 8 + (lane & 3) * 2];
            al[0] = *(const uint32_t*)&A_lo[r0 * 24 + (lane & 3) * 2];
            al[1] = *(const uint32_t*)&A_lo[(r0 + 8) * 24 + (lane & 3) * 2];
            al[2] = *(const uint32_t*)&A_lo[r0 * 24 + 8 + (lane & 3) * 2];
            al[3] = *(const uint32_t*)&A_lo[(r0 + 8) * 24 + 8 + (lane & 3) * 2];
#pragma unroll
            for (int nt = 0; nt < 4; nt++) {
                mma_f16(acc[mt][nt], ah, bh[nt]);   // hi*hi
                mma_f16(acc[mt][nt], ah, bl[nt]);   // hi*lo
                mma_f16(acc[mt][nt], al, bh[nt]);   // lo*hi
            }
        }
        __syncthreads();
    }

#pragma unroll
    for (int mt = 0; mt < 4; mt++) {
        int gr0 = rowBase + warp_m + mt * 16 + (lane >> 2);
#pragma unroll
        for (int nt = 0; nt < 4; nt++) {
            int col = colBase + warp_n + nt * 8 + (lane & 3) * 2;
            if (gr0 < NN) {
                *(float2*)&g_hp[(size_t)gr0 * 512 + col] = make_float2(acc[mt][nt][0], acc[mt][nt][1]);
                __half2 hv = __floats2half2_rn(acc[mt][nt][0], acc[mt][nt][1]);
                *(__half2*)&g_hph[(size_t)gr0 * 512 + col] = hv;
            }
            if (gr0 + 8 < NN) {
                *(float2*)&g_hp[(size_t)(gr0 + 8) * 512 + col] = make_float2(acc[mt][nt][2], acc[mt][nt][3]);
                __half2 hv = __floats2half2_rn(acc[mt][nt][2], acc[mt][nt][3]);
                *(__half2*)&g_hph[(size_t)(gr0 + 8) * 512 + col] = hv;
            }
        }
    }
}

// ---------------- attention coefficients s,d : [N,8] (reads f32 hp) -------------
__global__ void k_attn_coef(const float* __restrict__ asrc, const float* __restrict__ adst) {
    int g = blockIdx.x * blockDim.x + threadIdx.x;
    int n = g >> 5, lane = g & 31;
    if (n >= NN) return;
    int c0 = lane * 16;
    const float* row = &g_hp[(size_t)n * 512 + c0];
    float ps = 0.f, pd = 0.f;
#pragma unroll
    for (int u = 0; u < 16; u += 4) {
        float4 v = *(const float4*)&row[u];
        float4 a = *(const float4*)&asrc[c0 + u];
        float4 b = *(const float4*)&adst[c0 + u];
        ps += v.x * a.x + v.y * a.y + v.z * a.z + v.w * a.w;
        pd += v.x * b.x + v.y * b.y + v.z * b.z + v.w * b.w;
    }
    ps += __shfl_down_sync(0xffffffffu, ps, 2);
    pd += __shfl_down_sync(0xffffffffu, pd, 2);
    ps += __shfl_down_sync(0xffffffffu, ps, 1);
    pd += __shfl_down_sync(0xffffffffu, pd, 1);
    if ((lane & 3) == 0) {
        g_s[n * 8 + (lane >> 2)] = ps;
        g_d[n * 8 + (lane >> 2)] = pd;
    }
}

// ---------------- edge weights: w[j*8+h] = exp(leakyrelu(s[src]+d[dst])) --------
__global__ void k_edge_w() {
    int j = blockIdx.x * blockDim.x + threadIdx.x;
    if (j >= EPLUS) return;
    int sj = __ldg(&g_csr[j]);
    int dj = __ldg(&g_dstc[j]);
    const float4* sr = (const float4*)&g_s[sj * 8];
    const float4* dr = (const float4*)&g_d[dj * 8];
    float4 s0 = __ldg(&sr[0]), s1 = __ldg(&sr[1]);
    float4 d0 = __ldg(&dr[0]), d1 = __ldg(&dr[1]);
    float e[8] = { s0.x + d0.x, s0.y + d0.y, s0.z + d0.z, s0.w + d0.w,
                   s1.x + d1.x, s1.y + d1.y, s1.z + d1.z, s1.w + d1.w };
#pragma unroll
    for (int h = 0; h < 8; h++) {
        float v = e[h];
        v = (v > 0.f) ? v : NEG * v;
        e[h] = __expf(v);
    }
    float4* wp = (float4*)&g_w[(size_t)j * 8];
    wp[0] = make_float4(e[0], e[1], e[2], e[3]);
    wp[1] = make_float4(e[4], e[5], e[6], e[7]);
}

// ---------------- single-pass GAT aggregation (warp per node, precomputed w) ----
// lane loads 16B chunk i*32+lane of the fp16 row (8 channels); head = i*4+(lane>>3)
// mode 0: write fp16 hi/lo (next GEMM input); mode 1: write f32 g_hn (heads)
__global__ void k_gat_agg2(const float* __restrict__ bias, int mode) {
    int g = blockIdx.x * blockDim.x + threadIdx.x;
    int n = g >> 5, lane = g & 31;
    if (n >= NN) return;
    int start = g_off[n], end = g_off[n + 1];
    int h8 = lane & 7;

    float den = 0.f;
    float acc[16];
#pragma unroll
    for (int i = 0; i < 16; i++) acc[i] = 0.f;

#pragma unroll 4
    for (int j = start; j < end; j++) {
        float w = __ldg(&g_w[(size_t)j * 8 + h8]);   // no dependent chain
        den += w;
        int sj = __ldg(&g_csr[j]);
        const uint4* row = (const uint4*)&g_hph[(size_t)sj * 512];
#pragma unroll
        for (int i = 0; i < 2; i++) {
            int hh = i * 4 + (lane >> 3);          // head owning this 8-channel chunk
            float wi = __shfl_sync(0xffffffffu, w, hh);
            uint4 v = __ldg(&row[i * 32 + lane]);  // 8 halfs
            float2 p0 = __half22float2(*(__half2*)&v.x);
            float2 p1 = __half22float2(*(__half2*)&v.y);
            float2 p2 = __half22float2(*(__half2*)&v.z);
            float2 p3 = __half22float2(*(__half2*)&v.w);
            acc[i * 8 + 0] += wi * p0.x;
            acc[i * 8 + 1] += wi * p0.y;
            acc[i * 8 + 2] += wi * p1.x;
            acc[i * 8 + 3] += wi * p1.y;
            acc[i * 8 + 4] += wi * p2.x;
            acc[i * 8 + 5] += wi * p2.y;
            acc[i * 8 + 6] += wi * p3.x;
            acc[i * 8 + 7] += wi * p3.y;
        }
    }

#pragma unroll
    for (int i = 0; i < 2; i++) {
        int hh = i * 4 + (lane >> 3);
        float dh  = __shfl_sync(0xffffffffu, den, hh);
        float inv = 1.f / (dh + 1e-16f);
        int col = i * 256 + lane * 8;
#pragma unroll
        for (int q = 0; q < 2; q++) {
            int c4 = col + q * 4;
            float4 b = *(const float4*)&bias[c4];
            float4 o;
            o.x = fmaxf(acc[i * 8 + q * 4 + 0] * inv + b.x, 0.f);
            o.y = fmaxf(acc[i * 8 + q * 4 + 1] * inv + b.y, 0.f);
            o.z = fmaxf(acc[i * 8 + q * 4 + 2] * inv + b.z, 0.f);
            o.w = fmaxf(acc[i * 8 + q * 4 + 3] * inv + b.w, 0.f);
            if (mode) {
                *(float4*)&g_hn[(size_t)n * 512 + c4] = o;
            } else {
                __half hx, lx, hy, ly, hz, lz, hw, lw;
                f16_split(o.x, hx, lx); f16_split(o.y, hy, ly);
                f16_split(o.z, hz, lz); f16_split(o.w, hw, lw);
                __half2 h01 = __halves2half2(hx, hy), h23 = __halves2half2(hz, hw);
                __half2 l01 = __halves2half2(lx, ly), l23 = __halves2half2(lz, lw);
                *(uint2*)&g_Ah[(size_t)n * 512 + c4] =
                    make_uint2(*(uint32_t*)&h01, *(uint32_t*)&h23);
                *(uint2*)&g_Al[(size_t)n * 512 + c4] =
                    make_uint2(*(uint32_t*)&l01, *(uint32_t*)&l23);
            }
        }
    }
}

// ---------------- attention_weights head: softmax(h @ W_att + b) ----------------
__global__ void k_attw_sel(const float* __restrict__ W, const float* __restrict__ b,
                           float* __restrict__ out) {
    const float* h = g_hn;
    int g = blockIdx.x * blockDim.x + threadIdx.x;
    int n = g >> 5, lane = g & 31;
    if (n >= NN) return;
    int c0 = lane * 16;
    float p[8] = {0, 0, 0, 0, 0, 0, 0, 0};
#pragma unroll
    for (int u = 0; u < 16; u++) {
        float v = h[(size_t)n * 512 + c0 + u];
        float4 w0 = *(const float4*)&W[(c0 + u) * 8];
        float4 w1 = *(const float4*)&W[(c0 + u) * 8 + 4];
        p[0] += v * w0.x; p[1] += v * w0.y; p[2] += v * w0.z; p[3] += v * w0.w;
        p[4] += v * w1.x; p[5] += v * w1.y; p[6] += v * w1.z; p[7] += v * w1.w;
    }
#pragma unroll
    for (int o = 16; o; o >>= 1)
#pragma unroll
        for (int hh = 0; hh < 8; hh++) p[hh] += __shfl_xor_sync(0xffffffffu, p[hh], o);
    if (lane == 0) {
        float mx = -1e30f;
#pragma unroll
        for (int hh = 0; hh < 8; hh++) { p[hh] += b[hh]; mx = fmaxf(mx, p[hh]); }
        float sum = 0.f;
#pragma unroll
        for (int hh = 0; hh < 8; hh++) { p[hh] = __expf(p[hh] - mx); sum += p[hh]; }
        float is = 1.f / sum;
#pragma unroll
        for (int hh = 0; hh < 8; hh++) out[n * 8 + hh] = p[hh] * is;
    }
}

// ---------------- anomaly head: sigmoid(relu(h@W1+b1)@W2+b2) ----------------
__global__ __launch_bounds__(512)
void k_anomaly_sel(const float* __restrict__ W1, const float* __restrict__ b1,
                   const float* __restrict__ W2, const float* __restrict__ b2,
                   float* __restrict__ out) {
    const float* h = g_hn;
    __shared__ float hs[8][516];
    __shared__ float Ws[64][68];
    __shared__ float wsum[16];
    int tid = threadIdx.x;
    int n0 = blockIdx.x * 8;
#pragma unroll
    for (int sidx = 0; sidx < 8; sidx++) {
        int idx = sidx * 512 + tid;
        int rr = idx >> 9, cc = idx & 511;
        int n = n0 + rr;
        hs[rr][cc] = (n < NN) ? h[(size_t)n * 512 + cc] : 0.f;
    }
    int r = tid >> 6, c = tid & 63;
    float acc = 0.f;
    for (int k0 = 0; k0 < 512; k0 += 64) {
        __syncthreads();
#pragma unroll
        for (int sidx = 0; sidx < 8; sidx++) {
            int idx = sidx * 512 + tid;
            int kk = idx >> 6, cc2 = idx & 63;
            Ws[kk][cc2] = W1[(k0 + kk) * 64 + cc2];
        }
        __syncthreads();
#pragma unroll 16
        for (int k = 0; k < 64; k++) acc += hs[r][k0 + k] * Ws[k][c];
    }
    float t = fmaxf(acc + b1[c], 0.f);
    float part = t * W2[c];
#pragma unroll
    for (int o = 16; o; o >>= 1) part += __shfl_xor_sync(0xffffffffu, part, o);
    if ((tid & 31) == 0) wsum[tid >> 5] = part;
    __syncthreads();
    if ((tid & 63) == 0) {
        float sum = wsum[tid >> 5] + wsum[(tid >> 5) + 1];
        int n = n0 + r;
        if (n < NN) out[n] = 1.f / (1.f + __expf(-(sum + b2[0])));
    }
}

// ---------------- launch ----------------
#define GEMM_SMEM (2 * GBUF * 2)   // 2 buffers * 12288 halfs * 2 bytes = 49152

extern "C" void kernel_launch(void* const* d_in, const int* in_sizes, int n_in,
                              void* d_out, int out_size) {
    const float* x     = (const float*)d_in[0];
    const int*   ei    = (const int*)  d_in[1];
    const float* W_in  = (const float*)d_in[2];
    const float* b_in  = (const float*)d_in[3];
    const float* W_gat = (const float*)d_in[4];
    const float* a_src = (const float*)d_in[5];
    const float* a_dst = (const float*)d_in[6];
    const float* b_gat = (const float*)d_in[7];
    const float* W_att = (const float*)d_in[8];
    const float* b_att = (const float*)d_in[9];
    const float* W_h1  = (const float*)d_in[10];
    const float* b_h1  = (const float*)d_in[11];
    const float* W_h2  = (const float*)d_in[12];
    const float* b_h2  = (const float*)d_in[13];
    float* out = (float*)d_out;

    static int attr_done = 0;
    if (!attr_done) {
        cudaFuncSetAttribute(k_gemm_f16, cudaFuncAttributeMaxDynamicSharedMemorySize,
                             GEMM_SMEM);
        attr_done = 1;
    }

    dim3 grid(4, (NN + 127) / 128);

    // Launch order arranged so launch #4 = k_gemm_f16 (ncu capture slot).
    k_convB<<<256, 256>>>(W_gat, 0);                                    // 1
    k_convB<<<256, 256>>>(W_gat + (size_t)1 * 512 * 512, 1);            // 2
    k_input_proj<<<(NN + 7) / 8, 512>>>(x, W_in, b_in);                 // 3
    k_gemm_f16<<<grid, 256, GEMM_SMEM>>>(0);                            // 4  <- profiled
    k_convB<<<256, 256>>>(W_gat + (size_t)2 * 512 * 512, 2);            // 5

    // CSR by destination (independent of GEMM)
    k_init_counts<<<(NN + 255) / 256, 256>>>();                         // 6
    k_count<<<(EE + 255) / 256, 256>>>(ei);                             // 7
    k_scan<<<1, 1024>>>();                                              // 8
    k_scatter<<<(EPLUS + 255) / 256, 256>>>(ei);                        // 9

    // layer 0 tail
    k_attn_coef<<<(NN * 32 + 255) / 256, 256>>>(a_src, a_dst);          // 10
    k_edge_w<<<(EPLUS + 255) / 256, 256>>>();                           // 11
    k_gat_agg2<<<(NN * 32 + 255) / 256, 256>>>(b_gat, 0);               // 12

    // layers 1,2
    for (int l = 1; l < 3; l++) {
        k_gemm_f16<<<grid, 256, GEMM_SMEM>>>(l);
        k_attn_coef<<<(NN * 32 + 255) / 256, 256>>>(a_src + l * 512, a_dst + l * 512);
        k_edge_w<<<(EPLUS + 255) / 256, 256>>>();
        k_gat_agg2<<<(NN * 32 + 255) / 256, 256>>>(b_gat + l * 512, (l == 2) ? 1 : 0);
    }

    // heads: out[0:N) = anomaly scores, out[N:N+8N) = attention weights
    k_attw_sel<<<(NN * 32 + 255) / 256, 256>>>(W_att, b_att, out + NN);
    k_anomaly_sel<<<(NN + 7) / 8, 512>>>(W_h1, b_h1, W_h2, b_h2, out);
}

// round 15
// speedup vs baseline: 1.0353x; 1.0353x over previous
#include <cuda_runtime.h>
#include <cuda_fp16.h>
#include <math.h>
#include <stdint.h>

#define NN 30000
#define EE 480000
#define EPLUS (EE + NN)
#define NEG 0.2f

// ---------------- scratch (static device globals; no allocation) ----------------
__device__ float  g_hn[(size_t)NN * 512];   // final-layer f32 (heads input)
__device__ float  g_hp[(size_t)NN * 512];   // per-layer GEMM output (f32)
__device__ __half g_hph[(size_t)NN * 512];  // fp16 copy of hp (agg gather path)
__device__ __half g_Ah[(size_t)NN * 512];   // activations fp16 hi
__device__ __half g_Al[(size_t)NN * 512];   // activations fp16 lo
__device__ __half g_Bh[3 * 512 * 512];      // weights fp16 hi, per-layer, [N][K]
__device__ __half g_Bl[3 * 512 * 512];      // weights fp16 lo, per-layer
__device__ float  g_s [NN * 8];
__device__ float  g_d [NN * 8];
__device__ float  g_w [(size_t)EPLUS * 8];  // per-(edge,head) unnormalized weights
__device__ int    g_off[NN + 1];
__device__ int    g_cnt[NN];
__device__ int    g_cur[NN];
__device__ int    g_csr[EPLUS];
__device__ int    g_dstc[EPLUS];            // dst node of each CSR slot

// ---------------- helpers ----------------
__device__ __forceinline__ uint32_t smem_u32(const void* p) {
    return (uint32_t)__cvta_generic_to_shared(p);
}
__device__ __forceinline__ void cp_async16(uint32_t dst, const void* src, int src_bytes) {
    asm volatile("cp.async.cg.shared.global [%0], [%1], 16, %2;\n"
                 :: "r"(dst), "l"(src), "r"(src_bytes));
}
__device__ __forceinline__ void cp_commit() { asm volatile("cp.async.commit_group;\n"); }
template <int N>
__device__ __forceinline__ void cp_wait() { asm volatile("cp.async.wait_group %0;\n" :: "n"(N)); }

__device__ __forceinline__ void f16_split(float v, __half& hi, __half& lo) {
    hi = __float2half_rn(v);
    lo = __float2half_rn(v - __half2float(hi));
}

// fp16 mma m16n8k16, f32 accumulate
__device__ __forceinline__ void mma_f16(float* c, const uint32_t* a, const uint32_t* b) {
    asm volatile(
        "mma.sync.aligned.m16n8k16.row.col.f32.f16.f16.f32 "
        "{%0,%1,%2,%3}, {%4,%5,%6,%7}, {%8,%9}, {%0,%1,%2,%3};\n"
        : "+f"(c[0]), "+f"(c[1]), "+f"(c[2]), "+f"(c[3])
        : "r"(a[0]), "r"(a[1]), "r"(a[2]), "r"(a[3]), "r"(b[0]), "r"(b[1]));
}

// ldmatrix x4 (b16, non-transposed)
__device__ __forceinline__ void ldmx4(uint32_t* r, uint32_t addr) {
    asm volatile("ldmatrix.sync.aligned.m8n8.x4.shared.b16 {%0,%1,%2,%3}, [%4];"
                 : "=r"(r[0]), "=r"(r[1]), "=r"(r[2]), "=r"(r[3]) : "r"(addr));
}

// ---------------- CSR build ----------------
__global__ void k_init_counts() {
    int i = blockIdx.x * blockDim.x + threadIdx.x;
    if (i < NN) { g_cnt[i] = 1; g_cur[i] = 0; }
}

__global__ void k_count(const int* __restrict__ ei) {
    int i = blockIdx.x * blockDim.x + threadIdx.x;
    if (i < EE) atomicAdd(&g_cnt[ei[EE + i]], 1);
}

__global__ void k_scan() {
    __shared__ int sh[1024];
    __shared__ int carry;
    int tid = threadIdx.x;
    if (tid == 0) { carry = 0; g_off[0] = 0; }
    __syncthreads();
    for (int base = 0; base < NN; base += 1024) {
        int i = base + tid;
        int v = (i < NN) ? g_cnt[i] : 0;
        sh[tid] = v;
        __syncthreads();
        for (int o = 1; o < 1024; o <<= 1) {
            int t = (tid >= o) ? sh[tid - o] : 0;
            __syncthreads();
            sh[tid] += t;
            __syncthreads();
        }
        int inc = sh[tid] + carry;
        if (i < NN) g_off[i + 1] = inc;
        __syncthreads();
        if (tid == 1023) carry = inc;
        __syncthreads();
    }
}

__global__ void k_scatter(const int* __restrict__ ei) {
    int i = blockIdx.x * blockDim.x + threadIdx.x;
    if (i < EE) {
        int dst = ei[EE + i], src = ei[i];
        int p = atomicAdd(&g_cur[dst], 1);
        int slot = g_off[dst] + p;
        g_csr[slot]  = src;
        g_dstc[slot] = dst;
    } else if (i < EPLUS) {
        int n = i - EE;
        int p = atomicAdd(&g_cur[n], 1);
        int slot = g_off[n] + p;
        g_csr[slot]  = n;
        g_dstc[slot] = n;
    }
}

// ---------------- input projection: relu(x @ W_in + b) -> fp16 hi/lo ------------
__global__ void k_input_proj(const float* __restrict__ x, const float* __restrict__ W,
                             const float* __restrict__ b) {
    __shared__ float xs[8][32];
    int j  = threadIdx.x;
    int n0 = blockIdx.x * 8;
    if (j < 256) {
        int r = j >> 5, c = j & 31, n = n0 + r;
        xs[r][c] = (n < NN) ? x[n * 32 + c] : 0.f;
    }
    __syncthreads();
    float acc[8] = {0, 0, 0, 0, 0, 0, 0, 0};
#pragma unroll 8
    for (int k = 0; k < 32; k++) {
        float w = W[k * 512 + j];
#pragma unroll
        for (int r = 0; r < 8; r++) acc[r] += xs[r][k] * w;
    }
    float bb = b[j];
#pragma unroll
    for (int r = 0; r < 8; r++) {
        int n = n0 + r;
        if (n < NN) {
            float v = fmaxf(acc[r] + bb, 0.f);
            __half hi, lo;
            f16_split(v, hi, lo);
            g_Ah[(size_t)n * 512 + j] = hi;
            g_Al[(size_t)n * 512 + j] = lo;
        }
    }
}

// ---------------- weight conv: W[K][N] f32 -> transposed fp16 hi/lo [N][K] ------
__global__ void k_convB(const float* __restrict__ W, int layer) {
    int id = blockIdx.x * blockDim.x + threadIdx.x;  // 0..65535
    int n  = id >> 7;
    int k0 = (id & 127) * 4;
    size_t base = (size_t)layer * 512 * 512;
#pragma unroll
    for (int i = 0; i < 4; i++) {
        float v = __ldg(&W[(size_t)(k0 + i) * 512 + n]);
        __half hi, lo;
        f16_split(v, hi, lo);
        g_Bh[base + n * 512 + k0 + i] = hi;
        g_Bl[base + n * 512 + k0 + i] = lo;
    }
}

// ---------------- fp16-split tensor GEMM: g_hp = A[NN,512] @ B[512,512] ---------
// CTA 128x128, 8 warps, k-tile 16, double-buffered cp.async, ldmatrix fragments.
#define GBUF 12288

__device__ __forceinline__ void stage16(__half* sm, int buf, int k0, int rowBase,
                                        int colBase, int r, int c, size_t bbase) {
    uint32_t base = buf * GBUF;
    uint32_t dA = smem_u32(&sm[base + r * 24 + c * 8]);
    int gr = rowBase + r;
    int sz = (gr < NN) ? 16 : 0;
    size_t aoff = (size_t)(gr < NN ? gr : NN - 1) * 512 + k0 + c * 8;
    cp_async16(dA, &g_Ah[aoff], sz);
    cp_async16(smem_u32(&sm[base + 3072 + r * 24 + c * 8]), &g_Al[aoff], sz);
    size_t boff = bbase + (size_t)(colBase + r) * 512 + k0 + c * 8;
    cp_async16(smem_u32(&sm[base + 6144 + r * 24 + c * 8]), &g_Bh[boff], 16);
    cp_async16(smem_u32(&sm[base + 9216 + r * 24 + c * 8]), &g_Bl[boff], 16);
}

__global__ __launch_bounds__(256, 2)
void k_gemm_f16(int layer) {
    extern __shared__ __half sm[];
    int tid  = threadIdx.x;
    int lane = tid & 31;
    int warp = tid >> 5;
    int warp_m = (warp & 1) * 64;
    int warp_n = (warp >> 1) * 32;
    int rowBase = blockIdx.y * 128;
    int colBase = blockIdx.x * 128;
    size_t bbase = (size_t)layer * 512 * 512;

    int ldr = tid >> 1, ldc = tid & 1;

    // ldmatrix lane-address components (shared across all tiles)
    int lm_r  = ((lane >> 3) & 1) * 8 + (lane & 7);  // row within 16-row tile
    int lm_k  = (lane >> 4) * 8;                      // k offset (A)
    int lm_nr = (lane >> 4) * 8 + (lane & 7);         // n row within 16 (B)
    int lm_bk = ((lane >> 3) & 1) * 8;                // k offset (B)

    float acc[4][4][4];
#pragma unroll
    for (int i = 0; i < 4; i++)
#pragma unroll
        for (int j = 0; j < 4; j++)
#pragma unroll
            for (int k = 0; k < 4; k++) acc[i][j][k] = 0.f;

    stage16(sm, 0, 0, rowBase, colBase, ldr, ldc, bbase);
    cp_commit();

    for (int t = 0; t < 32; t++) {
        if (t < 31) {
            stage16(sm, (t + 1) & 1, (t + 1) * 16, rowBase, colBase, ldr, ldc, bbase);
            cp_commit();
            cp_wait<1>();
        } else {
            cp_wait<0>();
        }
        __syncthreads();

        const __half* A_hi = &sm[(t & 1) * GBUF];
        const __half* A_lo = A_hi + 3072;
        const __half* B_hi = A_hi + 6144;
        const __half* B_lo = A_hi + 9216;

        // B fragments: 2 ldmatrix.x4 per hi/lo (each covers 2 nt tiles, full k16)
        uint32_t bh[4][2], bl[4][2];
#pragma unroll
        for (int np = 0; np < 2; np++) {
            int nrow = warp_n + np * 16 + lm_nr;
            uint32_t rr[4];
            ldmx4(rr, smem_u32(&B_hi[nrow * 24 + lm_bk]));
            bh[np * 2][0] = rr[0]; bh[np * 2][1] = rr[1];
            bh[np * 2 + 1][0] = rr[2]; bh[np * 2 + 1][1] = rr[3];
            ldmx4(rr, smem_u32(&B_lo[nrow * 24 + lm_bk]));
            bl[np * 2][0] = rr[0]; bl[np * 2][1] = rr[1];
            bl[np * 2 + 1][0] = rr[2]; bl[np * 2 + 1][1] = rr[3];
        }
#pragma unroll
        for (int mt = 0; mt < 4; mt++) {
            int arow = warp_m + mt * 16 + lm_r;
            uint32_t ah[4], al[4];
            ldmx4(ah, smem_u32(&A_hi[arow * 24 + lm_k]));
            ldmx4(al, smem_u32(&A_lo[arow * 24 + lm_k]));
#pragma unroll
            for (int nt = 0; nt < 4; nt++) {
                mma_f16(acc[mt][nt], ah, bh[nt]);   // hi*hi
                mma_f16(acc[mt][nt], ah, bl[nt]);   // hi*lo
                mma_f16(acc[mt][nt], al, bh[nt]);   // lo*hi
            }
        }
        __syncthreads();
    }

#pragma unroll
    for (int mt = 0; mt < 4; mt++) {
        int gr0 = rowBase + warp_m + mt * 16 + (lane >> 2);
#pragma unroll
        for (int nt = 0; nt < 4; nt++) {
            int col = colBase + warp_n + nt * 8 + (lane & 3) * 2;
            if (gr0 < NN) {
                *(float2*)&g_hp[(size_t)gr0 * 512 + col] = make_float2(acc[mt][nt][0], acc[mt][nt][1]);
                __half2 hv = __floats2half2_rn(acc[mt][nt][0], acc[mt][nt][1]);
                *(__half2*)&g_hph[(size_t)gr0 * 512 + col] = hv;
            }
            if (gr0 + 8 < NN) {
                *(float2*)&g_hp[(size_t)(gr0 + 8) * 512 + col] = make_float2(acc[mt][nt][2], acc[mt][nt][3]);
                __half2 hv = __floats2half2_rn(acc[mt][nt][2], acc[mt][nt][3]);
                *(__half2*)&g_hph[(size_t)(gr0 + 8) * 512 + col] = hv;
            }
        }
    }
}

// ---------------- attention coefficients s,d : [N,8] (reads f32 hp) -------------
__global__ void k_attn_coef(const float* __restrict__ asrc, const float* __restrict__ adst) {
    int g = blockIdx.x * blockDim.x + threadIdx.x;
    int n = g >> 5, lane = g & 31;
    if (n >= NN) return;
    int c0 = lane * 16;
    const float* row = &g_hp[(size_t)n * 512 + c0];
    float ps = 0.f, pd = 0.f;
#pragma unroll
    for (int u = 0; u < 16; u += 4) {
        float4 v = *(const float4*)&row[u];
        float4 a = *(const float4*)&asrc[c0 + u];
        float4 b = *(const float4*)&adst[c0 + u];
        ps += v.x * a.x + v.y * a.y + v.z * a.z + v.w * a.w;
        pd += v.x * b.x + v.y * b.y + v.z * b.z + v.w * b.w;
    }
    ps += __shfl_down_sync(0xffffffffu, ps, 2);
    pd += __shfl_down_sync(0xffffffffu, pd, 2);
    ps += __shfl_down_sync(0xffffffffu, ps, 1);
    pd += __shfl_down_sync(0xffffffffu, pd, 1);
    if ((lane & 3) == 0) {
        g_s[n * 8 + (lane >> 2)] = ps;
        g_d[n * 8 + (lane >> 2)] = pd;
    }
}

// ---------------- edge weights: w[j*8+h] = exp(leakyrelu(s[src]+d[dst])) --------
__global__ void k_edge_w() {
    int j = blockIdx.x * blockDim.x + threadIdx.x;
    if (j >= EPLUS) return;
    int sj = __ldg(&g_csr[j]);
    int dj = __ldg(&g_dstc[j]);
    const float4* sr = (const float4*)&g_s[sj * 8];
    const float4* dr = (const float4*)&g_d[dj * 8];
    float4 s0 = __ldg(&sr[0]), s1 = __ldg(&sr[1]);
    float4 d0 = __ldg(&dr[0]), d1 = __ldg(&dr[1]);
    float e[8] = { s0.x + d0.x, s0.y + d0.y, s0.z + d0.z, s0.w + d0.w,
                   s1.x + d1.x, s1.y + d1.y, s1.z + d1.z, s1.w + d1.w };
#pragma unroll
    for (int h = 0; h < 8; h++) {
        float v = e[h];
        v = (v > 0.f) ? v : NEG * v;
        e[h] = __expf(v);
    }
    float4* wp = (float4*)&g_w[(size_t)j * 8];
    wp[0] = make_float4(e[0], e[1], e[2], e[3]);
    wp[1] = make_float4(e[4], e[5], e[6], e[7]);
}

// ---------------- single-pass GAT aggregation (warp per node, precomputed w) ----
__global__ void k_gat_agg2(const float* __restrict__ bias, int mode) {
    int g = blockIdx.x * blockDim.x + threadIdx.x;
    int n = g >> 5, lane = g & 31;
    if (n >= NN) return;
    int start = g_off[n], end = g_off[n + 1];
    int h8 = lane & 7;

    float den = 0.f;
    float acc[16];
#pragma unroll
    for (int i = 0; i < 16; i++) acc[i] = 0.f;

#pragma unroll 2
    for (int j = start; j < end; j++) {
        float w = __ldg(&g_w[(size_t)j * 8 + h8]);   // no dependent chain
        den += w;
        int sj = __ldg(&g_csr[j]);
        const uint4* row = (const uint4*)&g_hph[(size_t)sj * 512];
#pragma unroll
        for (int i = 0; i < 2; i++) {
            int hh = i * 4 + (lane >> 3);          // head owning this 8-channel chunk
            float wi = __shfl_sync(0xffffffffu, w, hh);
            uint4 v = __ldg(&row[i * 32 + lane]);  // 8 halfs
            float2 p0 = __half22float2(*(__half2*)&v.x);
            float2 p1 = __half22float2(*(__half2*)&v.y);
            float2 p2 = __half22float2(*(__half2*)&v.z);
            float2 p3 = __half22float2(*(__half2*)&v.w);
            acc[i * 8 + 0] += wi * p0.x;
            acc[i * 8 + 1] += wi * p0.y;
            acc[i * 8 + 2] += wi * p1.x;
            acc[i * 8 + 3] += wi * p1.y;
            acc[i * 8 + 4] += wi * p2.x;
            acc[i * 8 + 5] += wi * p2.y;
            acc[i * 8 + 6] += wi * p3.x;
            acc[i * 8 + 7] += wi * p3.y;
        }
    }

#pragma unroll
    for (int i = 0; i < 2; i++) {
        int hh = i * 4 + (lane >> 3);
        float dh  = __shfl_sync(0xffffffffu, den, hh);
        float inv = 1.f / (dh + 1e-16f);
        int col = i * 256 + lane * 8;
#pragma unroll
        for (int q = 0; q < 2; q++) {
            int c4 = col + q * 4;
            float4 b = *(const float4*)&bias[c4];
            float4 o;
            o.x = fmaxf(acc[i * 8 + q * 4 + 0] * inv + b.x, 0.f);
            o.y = fmaxf(acc[i * 8 + q * 4 + 1] * inv + b.y, 0.f);
            o.z = fmaxf(acc[i * 8 + q * 4 + 2] * inv + b.z, 0.f);
            o.w = fmaxf(acc[i * 8 + q * 4 + 3] * inv + b.w, 0.f);
            if (mode) {
                *(float4*)&g_hn[(size_t)n * 512 + c4] = o;
            } else {
                __half hx, lx, hy, ly, hz, lz, hw, lw;
                f16_split(o.x, hx, lx); f16_split(o.y, hy, ly);
                f16_split(o.z, hz, lz); f16_split(o.w, hw, lw);
                __half2 h01 = __halves2half2(hx, hy), h23 = __halves2half2(hz, hw);
                __half2 l01 = __halves2half2(lx, ly), l23 = __halves2half2(lz, lw);
                *(uint2*)&g_Ah[(size_t)n * 512 + c4] =
                    make_uint2(*(uint32_t*)&h01, *(uint32_t*)&h23);
                *(uint2*)&g_Al[(size_t)n * 512 + c4] =
                    make_uint2(*(uint32_t*)&l01, *(uint32_t*)&l23);
            }
        }
    }
}

// ---------------- attention_weights head: softmax(h @ W_att + b) ----------------
__global__ void k_attw_sel(const float* __restrict__ W, const float* __restrict__ b,
                           float* __restrict__ out) {
    const float* h = g_hn;
    int g = blockIdx.x * blockDim.x + threadIdx.x;
    int n = g >> 5, lane = g & 31;
    if (n >= NN) return;
    int c0 = lane * 16;
    float p[8] = {0, 0, 0, 0, 0, 0, 0, 0};
#pragma unroll
    for (int u = 0; u < 16; u++) {
        float v = h[(size_t)n * 512 + c0 + u];
        float4 w0 = *(const float4*)&W[(c0 + u) * 8];
        float4 w1 = *(const float4*)&W[(c0 + u) * 8 + 4];
        p[0] += v * w0.x; p[1] += v * w0.y; p[2] += v * w0.z; p[3] += v * w0.w;
        p[4] += v * w1.x; p[5] += v * w1.y; p[6] += v * w1.z; p[7] += v * w1.w;
    }
#pragma unroll
    for (int o = 16; o; o >>= 1)
#pragma unroll
        for (int hh = 0; hh < 8; hh++) p[hh] += __shfl_xor_sync(0xffffffffu, p[hh], o);
    if (lane == 0) {
        float mx = -1e30f;
#pragma unroll
        for (int hh = 0; hh < 8; hh++) { p[hh] += b[hh]; mx = fmaxf(mx, p[hh]); }
        float sum = 0.f;
#pragma unroll
        for (int hh = 0; hh < 8; hh++) { p[hh] = __expf(p[hh] - mx); sum += p[hh]; }
        float is = 1.f / sum;
#pragma unroll
        for (int hh = 0; hh < 8; hh++) out[n * 8 + hh] = p[hh] * is;
    }
}

// ---------------- anomaly head: sigmoid(relu(h@W1+b1)@W2+b2) ----------------
__global__ __launch_bounds__(512)
void k_anomaly_sel(const float* __restrict__ W1, const float* __restrict__ b1,
                   const float* __restrict__ W2, const float* __restrict__ b2,
                   float* __restrict__ out) {
    const float* h = g_hn;
    __shared__ float hs[8][516];
    __shared__ float Ws[64][68];
    __shared__ float wsum[16];
    int tid = threadIdx.x;
    int n0 = blockIdx.x * 8;
#pragma unroll
    for (int sidx = 0; sidx < 8; sidx++) {
        int idx = sidx * 512 + tid;
        int rr = idx >> 9, cc = idx & 511;
        int n = n0 + rr;
        hs[rr][cc] = (n < NN) ? h[(size_t)n * 512 + cc] : 0.f;
    }
    int r = tid >> 6, c = tid & 63;
    float acc = 0.f;
    for (int k0 = 0; k0 < 512; k0 += 64) {
        __syncthreads();
#pragma unroll
        for (int sidx = 0; sidx < 8; sidx++) {
            int idx = sidx * 512 + tid;
            int kk = idx >> 6, cc2 = idx & 63;
            Ws[kk][cc2] = W1[(k0 + kk) * 64 + cc2];
        }
        __syncthreads();
#pragma unroll 16
        for (int k = 0; k < 64; k++) acc += hs[r][k0 + k] * Ws[k][c];
    }
    float t = fmaxf(acc + b1[c], 0.f);
    float part = t * W2[c];
#pragma unroll
    for (int o = 16; o; o >>= 1) part += __shfl_xor_sync(0xffffffffu, part, o);
    if ((tid & 31) == 0) wsum[tid >> 5] = part;
    __syncthreads();
    if ((tid & 63) == 0) {
        float sum = wsum[tid >> 5] + wsum[(tid >> 5) + 1];
        int n = n0 + r;
        if (n < NN) out[n] = 1.f / (1.f + __expf(-(sum + b2[0])));
    }
}

// ---------------- launch ----------------
#define GEMM_SMEM (2 * GBUF * 2)   // 2 buffers * 12288 halfs * 2 bytes = 49152

extern "C" void kernel_launch(void* const* d_in, const int* in_sizes, int n_in,
                              void* d_out, int out_size) {
    const float* x     = (const float*)d_in[0];
    const int*   ei    = (const int*)  d_in[1];
    const float* W_in  = (const float*)d_in[2];
    const float* b_in  = (const float*)d_in[3];
    const float* W_gat = (const float*)d_in[4];
    const float* a_src = (const float*)d_in[5];
    const float* a_dst = (const float*)d_in[6];
    const float* b_gat = (const float*)d_in[7];
    const float* W_att = (const float*)d_in[8];
    const float* b_att = (const float*)d_in[9];
    const float* W_h1  = (const float*)d_in[10];
    const float* b_h1  = (const float*)d_in[11];
    const float* W_h2  = (const float*)d_in[12];
    const float* b_h2  = (const float*)d_in[13];
    float* out = (float*)d_out;

    static int attr_done = 0;
    if (!attr_done) {
        cudaFuncSetAttribute(k_gemm_f16, cudaFuncAttributeMaxDynamicSharedMemorySize,
                             GEMM_SMEM);
        attr_done = 1;
    }

    dim3 grid(4, (NN + 127) / 128);

    // Launch order arranged so launch #4 = k_gemm_f16 (ncu capture slot).
    k_convB<<<256, 256>>>(W_gat, 0);                                    // 1
    k_convB<<<256, 256>>>(W_gat + (size_t)1 * 512 * 512, 1);            // 2
    k_input_proj<<<(NN + 7) / 8, 512>>>(x, W_in, b_in);                 // 3
    k_gemm_f16<<<grid, 256, GEMM_SMEM>>>(0);                            // 4  <- profiled
    k_convB<<<256, 256>>>(W_gat + (size_t)2 * 512 * 512, 2);            // 5

    // CSR by destination (independent of GEMM)
    k_init_counts<<<(NN + 255) / 256, 256>>>();                         // 6
    k_count<<<(EE + 255) / 256, 256>>>(ei);                             // 7
    k_scan<<<1, 1024>>>();                                              // 8
    k_scatter<<<(EPLUS + 255) / 256, 256>>>(ei);                        // 9

    // layer 0 tail
    k_attn_coef<<<(NN * 32 + 255) / 256, 256>>>(a_src, a_dst);          // 10
    k_edge_w<<<(EPLUS + 255) / 256, 256>>>();                           // 11
    k_gat_agg2<<<(NN * 32 + 255) / 256, 256>>>(b_gat, 0);               // 12

    // layers 1,2
    for (int l = 1; l < 3; l++) {
        k_gemm_f16<<<grid, 256, GEMM_SMEM>>>(l);
        k_attn_coef<<<(NN * 32 + 255) / 256, 256>>>(a_src + l * 512, a_dst + l * 512);
        k_edge_w<<<(EPLUS + 255) / 256, 256>>>();
        k_gat_agg2<<<(NN * 32 + 255) / 256, 256>>>(b_gat + l * 512, (l == 2) ? 1 : 0);
    }

    // heads: out[0:N) = anomaly scores, out[N:N+8N) = attention weights
    k_attw_sel<<<(NN * 32 + 255) / 256, 256>>>(W_att, b_att, out + NN);
    k_anomaly_sel<<<(NN + 7) / 8, 512>>>(W_h1, b_h1, W_h2, b_h2, out);
}